// round 1
// baseline (speedup 1.0000x reference)
#include <cuda_runtime.h>
#include <math.h>

#define BATCH   2
#define SEQL    2048
#define DEMB    2048
#define NHEADS  16
#define DHEAD   128
#define NTOK    (BATCH * SEQL)       // 4096
#define D3      (3 * DEMB)           // 6144

typedef unsigned long long ull;

// Scratch (allocation-free rule: __device__ globals)
__device__ float g_qkv[(size_t)NTOK * D3];     // 96 MB
__device__ float g_attn[(size_t)NTOK * DEMB];  // 32 MB

// ---------------- packed f32x2 helpers (sm_100+) ----------------
__device__ __forceinline__ ull pack2(float x, float y) {
    ull r; asm("mov.b64 %0, {%1, %2};" : "=l"(r) : "f"(x), "f"(y)); return r;
}
__device__ __forceinline__ void unpack2(ull v, float &x, float &y) {
    asm("mov.b64 {%0, %1}, %2;" : "=f"(x), "=f"(y) : "l"(v));
}
__device__ __forceinline__ void fma2(ull &d, ull a, ull b) {
    asm("fma.rn.f32x2 %0, %1, %2, %0;" : "+l"(d) : "l"(a), "l"(b));
}
__device__ __forceinline__ void mul2(ull &d, ull a) {
    asm("mul.rn.f32x2 %0, %0, %1;" : "+l"(d) : "l"(a));
}

union F4U { float4 f4; ull u[2]; float f[4]; };

// ================================================================
// SGEMM: C[M,N] = A[M,K] @ B[K,N] + bias[N]
// 128x128x16 tile, 256 threads, 8x8 per-thread via f32x2
// Requires M%128==0, N%128==0, K%16==0 (true for all our shapes)
// ================================================================
__global__ __launch_bounds__(256) void sgemm_bias_kernel(
    const float* __restrict__ A, const float* __restrict__ B,
    const float* __restrict__ bias, float* __restrict__ C,
    int M, int N, int K)
{
    __shared__ float As[16][132];   // A^T tile: As[k][m]
    __shared__ float Bs[16][128];   // Bs[k][n]

    const int tid = threadIdx.x;
    const int tx = tid & 15, ty = tid >> 4;
    const int bm = blockIdx.y * 128, bn = blockIdx.x * 128;

    ull acc[8][4];
    #pragma unroll
    for (int i = 0; i < 8; i++)
        #pragma unroll
        for (int j = 0; j < 4; j++) acc[i][j] = 0ull;

    for (int k0 = 0; k0 < K; k0 += 16) {
        // Load A tile (128 x 16), store transposed
        #pragma unroll
        for (int it = 0; it < 2; it++) {
            int idx = tid + it * 256;          // 0..511
            int row = idx >> 2;                // 0..127
            int kq  = (idx & 3) * 4;           // 0,4,8,12
            float4 f = *(const float4*)(A + (size_t)(bm + row) * K + k0 + kq);
            As[kq + 0][row] = f.x; As[kq + 1][row] = f.y;
            As[kq + 2][row] = f.z; As[kq + 3][row] = f.w;
        }
        // Load B tile (16 x 128)
        #pragma unroll
        for (int it = 0; it < 2; it++) {
            int idx = tid + it * 256;
            int row = idx >> 5;                // 0..15
            int cq  = (idx & 31) * 4;          // 0..124
            *(float4*)&Bs[row][cq] = *(const float4*)(B + (size_t)(k0 + row) * N + bn + cq);
        }
        __syncthreads();

        #pragma unroll
        for (int kk = 0; kk < 16; kk++) {
            F4U a0, a1, b0, b1;
            a0.f4 = *(const float4*)&As[kk][ty * 8];
            a1.f4 = *(const float4*)&As[kk][ty * 8 + 4];
            b0.f4 = *(const float4*)&Bs[kk][tx * 8];
            b1.f4 = *(const float4*)&Bs[kk][tx * 8 + 4];
            ull bb[4] = { b0.u[0], b0.u[1], b1.u[0], b1.u[1] };
            #pragma unroll
            for (int i = 0; i < 8; i++) {
                float av = (i < 4) ? a0.f[i] : a1.f[i - 4];
                ull ad = pack2(av, av);
                #pragma unroll
                for (int j = 0; j < 4; j++) fma2(acc[i][j], ad, bb[j]);
            }
        }
        __syncthreads();
    }

    // Epilogue: add bias, store
    const int n = bn + tx * 8;
    float4 bi0 = *(const float4*)(bias + n);
    float4 bi1 = *(const float4*)(bias + n + 4);
    #pragma unroll
    for (int i = 0; i < 8; i++) {
        float r[8];
        #pragma unroll
        for (int j = 0; j < 4; j++) unpack2(acc[i][j], r[2 * j], r[2 * j + 1]);
        float4 o0 = make_float4(r[0] + bi0.x, r[1] + bi0.y, r[2] + bi0.z, r[3] + bi0.w);
        float4 o1 = make_float4(r[4] + bi1.x, r[5] + bi1.y, r[6] + bi1.z, r[7] + bi1.w);
        size_t off = (size_t)(bm + ty * 8 + i) * N + n;
        *(float4*)(C + off)     = o0;
        *(float4*)(C + off + 4) = o1;
    }
}

// ================================================================
// Causal flash attention, fp32, 128x128 tiles, f32x2 inner loops.
// Block: 256 threads; grid: (S/128, H, B).
// Smem: Qs[k][q] (transposed), KPs (K transposed, reused for P^T),
//       Vs[kj][d] row-major.  3 * 128*132 floats + 3*128 = 204,288 B.
// ================================================================
#define LDS_S 132
#define FLASH_SMEM ((3 * 128 * LDS_S + 3 * 128) * (int)sizeof(float))

__global__ __launch_bounds__(256, 1) void flash_attn_kernel(
    const float* __restrict__ qkv, float* __restrict__ attn_out)
{
    extern __shared__ float sm[];
    float* Qs  = sm;                    // [128][132]  Qs[k][q]
    float* KPs = Qs  + 128 * LDS_S;     // [128][132]  Ks[k][kj] then P^T[kj][q]
    float* Vs  = KPs + 128 * LDS_S;     // [128][132]  Vs[kj][d]
    float* m_s = Vs  + 128 * LDS_S;     // [128]
    float* l_s = m_s + 128;             // [128]
    float* f_s = l_s + 128;             // [128]

    const int qt  = (int)gridDim.x - 1 - (int)blockIdx.x;  // heavy tiles first
    const int h   = blockIdx.y;
    const int b   = blockIdx.z;
    const int tid = threadIdx.x;
    const int tx = tid & 15, ty = tid >> 4;
    const int r0 = ty * 8, c0 = tx * 8;
    const float scale = 0.08838834764831845f;  // 1/sqrt(128)

    // Load Q tile transposed: Qs[k][q]
    #pragma unroll
    for (int it = 0; it < 16; it++) {
        int idx = tid + it * 256;              // 0..4095
        int r  = idx >> 5;                     // q row 0..127
        int c4 = (idx & 31) * 4;               // head-dim offset
        float4 f = *(const float4*)(qkv + (size_t)(b * SEQL + qt * 128 + r) * D3 + h * DHEAD + c4);
        Qs[(c4 + 0) * LDS_S + r] = f.x; Qs[(c4 + 1) * LDS_S + r] = f.y;
        Qs[(c4 + 2) * LDS_S + r] = f.z; Qs[(c4 + 3) * LDS_S + r] = f.w;
    }
    if (tid < 128) { m_s[tid] = -INFINITY; l_s[tid] = 0.0f; }

    ull o2[8][4];
    #pragma unroll
    for (int i = 0; i < 8; i++)
        #pragma unroll
        for (int j = 0; j < 4; j++) o2[i][j] = 0ull;

    __syncthreads();

    for (int jt = 0; jt <= qt; jt++) {
        // ---- load K (transposed) and V (row-major) tiles ----
        #pragma unroll
        for (int it = 0; it < 16; it++) {
            int idx = tid + it * 256;
            int r  = idx >> 5;
            int c4 = (idx & 31) * 4;
            size_t go = (size_t)(b * SEQL + jt * 128 + r) * D3 + h * DHEAD + c4;
            float4 kf = *(const float4*)(qkv + go + DEMB);
            KPs[(c4 + 0) * LDS_S + r] = kf.x; KPs[(c4 + 1) * LDS_S + r] = kf.y;
            KPs[(c4 + 2) * LDS_S + r] = kf.z; KPs[(c4 + 3) * LDS_S + r] = kf.w;
            *(float4*)&Vs[r * LDS_S + c4] = *(const float4*)(qkv + go + 2 * DEMB);
        }
        __syncthreads();

        // ---- scores: S = Q @ K^T  (8x8 per thread) ----
        ull s2[8][4];
        #pragma unroll
        for (int i = 0; i < 8; i++)
            #pragma unroll
            for (int j = 0; j < 4; j++) s2[i][j] = 0ull;

        for (int k = 0; k < 128; k++) {
            F4U a0, a1, b0, b1;
            a0.f4 = *(const float4*)&Qs[k * LDS_S + r0];
            a1.f4 = *(const float4*)&Qs[k * LDS_S + r0 + 4];
            b0.f4 = *(const float4*)&KPs[k * LDS_S + c0];
            b1.f4 = *(const float4*)&KPs[k * LDS_S + c0 + 4];
            ull bb[4] = { b0.u[0], b0.u[1], b1.u[0], b1.u[1] };
            #pragma unroll
            for (int i = 0; i < 8; i++) {
                float av = (i < 4) ? a0.f[i] : a1.f[i - 4];
                ull ad = pack2(av, av);
                #pragma unroll
                for (int j = 0; j < 4; j++) fma2(s2[i][j], ad, bb[j]);
            }
        }

        // ---- unpack, mask (diag tile), scale ----
        float sc[8][8];
        #pragma unroll
        for (int i = 0; i < 8; i++)
            #pragma unroll
            for (int j = 0; j < 4; j++) unpack2(s2[i][j], sc[i][2 * j], sc[i][2 * j + 1]);
        if (jt == qt) {
            #pragma unroll
            for (int i = 0; i < 8; i++)
                #pragma unroll
                for (int j = 0; j < 8; j++)
                    if (c0 + j > r0 + i) sc[i][j] = -INFINITY;
        }
        #pragma unroll
        for (int i = 0; i < 8; i++)
            #pragma unroll
            for (int j = 0; j < 8; j++) sc[i][j] *= scale;

        __syncthreads();   // everyone done reading K from KPs

        // ---- write P^T into KPs: KPs[kj][q] ----
        #pragma unroll
        for (int j = 0; j < 8; j++) {
            float4 p0 = make_float4(sc[0][j], sc[1][j], sc[2][j], sc[3][j]);
            float4 p1 = make_float4(sc[4][j], sc[5][j], sc[6][j], sc[7][j]);
            *(float4*)&KPs[(c0 + j) * LDS_S + r0]     = p0;
            *(float4*)&KPs[(c0 + j) * LDS_S + r0 + 4] = p1;
        }
        __syncthreads();

        // ---- online softmax (one thread per q-row) ----
        if (tid < 128) {
            const int q = tid;
            float mo = m_s[q], lo = l_s[q];
            float mt = -INFINITY;
            #pragma unroll 4
            for (int c = 0; c < 128; c++) mt = fmaxf(mt, KPs[c * LDS_S + q]);
            float mn = fmaxf(mo, mt);
            float f = __expf(mo - mn);       // 0 on first tile (mo = -inf)
            float ssum = 0.0f;
            #pragma unroll 4
            for (int c = 0; c < 128; c++) {
                float p = __expf(KPs[c * LDS_S + q] - mn);
                KPs[c * LDS_S + q] = p;
                ssum += p;
            }
            m_s[q] = mn;
            l_s[q] = lo * f + ssum;
            f_s[q] = f;
        }
        __syncthreads();

        // ---- rescale O, then O += P @ V ----
        #pragma unroll
        for (int i = 0; i < 8; i++) {
            float fv = f_s[r0 + i];
            ull fd = pack2(fv, fv);
            #pragma unroll
            for (int j = 0; j < 4; j++) mul2(o2[i][j], fd);
        }
        for (int kk = 0; kk < 128; kk++) {
            F4U a0, a1, b0, b1;
            a0.f4 = *(const float4*)&KPs[kk * LDS_S + r0];       // P^T[kk][q]
            a1.f4 = *(const float4*)&KPs[kk * LDS_S + r0 + 4];
            b0.f4 = *(const float4*)&Vs[kk * LDS_S + c0];        // V[kk][d]
            b1.f4 = *(const float4*)&Vs[kk * LDS_S + c0 + 4];
            ull bb[4] = { b0.u[0], b0.u[1], b1.u[0], b1.u[1] };
            #pragma unroll
            for (int i = 0; i < 8; i++) {
                float av = (i < 4) ? a0.f[i] : a1.f[i - 4];
                ull ad = pack2(av, av);
                #pragma unroll
                for (int j = 0; j < 4; j++) fma2(o2[i][j], ad, bb[j]);
            }
        }
        __syncthreads();   // before next tile's loads overwrite KPs/Vs
    }

    // ---- finalize: O /= l, write [B,S,H*dh] ----
    #pragma unroll
    for (int i = 0; i < 8; i++) {
        float inv = 1.0f / l_s[r0 + i];
        float r[8];
        #pragma unroll
        for (int j = 0; j < 4; j++) unpack2(o2[i][j], r[2 * j], r[2 * j + 1]);
        float4 o0 = make_float4(r[0] * inv, r[1] * inv, r[2] * inv, r[3] * inv);
        float4 o1 = make_float4(r[4] * inv, r[5] * inv, r[6] * inv, r[7] * inv);
        size_t off = (size_t)(b * SEQL + qt * 128 + r0 + i) * DEMB + h * DHEAD + c0;
        *(float4*)(attn_out + off)     = o0;
        *(float4*)(attn_out + off + 4) = o1;
    }
}

// ================================================================
// Launcher
// ================================================================
extern "C" void kernel_launch(void* const* d_in, const int* in_sizes, int n_in,
                              void* d_out, int out_size)
{
    (void)in_sizes; (void)n_in; (void)out_size;
    const float* x     = (const float*)d_in[0];
    const float* w_in  = (const float*)d_in[1];
    const float* b_in  = (const float*)d_in[2];
    const float* w_out = (const float*)d_in[3];
    const float* b_out = (const float*)d_in[4];
    float* out = (float*)d_out;

    void* qkv_ptr  = nullptr;
    void* attn_ptr = nullptr;
    cudaGetSymbolAddress(&qkv_ptr,  g_qkv);
    cudaGetSymbolAddress(&attn_ptr, g_attn);

    cudaFuncSetAttribute(flash_attn_kernel,
                         cudaFuncAttributeMaxDynamicSharedMemorySize, FLASH_SMEM);

    // 1) qkv = x @ w_in + b_in        [4096, 6144]
    dim3 g1(D3 / 128, NTOK / 128);
    sgemm_bias_kernel<<<g1, 256>>>(x, w_in, b_in, (float*)qkv_ptr, NTOK, D3, DEMB);

    // 2) causal flash attention       -> g_attn [4096, 2048]
    dim3 g2(SEQL / 128, NHEADS, BATCH);
    flash_attn_kernel<<<g2, 256, FLASH_SMEM>>>((const float*)qkv_ptr, (float*)attn_ptr);

    // 3) out = attn @ w_out + b_out   [4096, 2048]
    dim3 g3(DEMB / 128, NTOK / 128);
    sgemm_bias_kernel<<<g3, 256>>>((const float*)attn_ptr, w_out, b_out, out, NTOK, DEMB, DEMB);
}

// round 3
// speedup vs baseline: 1.9295x; 1.9295x over previous
#include <cuda_runtime.h>
#include <math.h>
#include <stdint.h>

#define BATCH   2
#define SEQL    2048
#define DEMB    2048
#define NHEADS  16
#define DHEAD   128
#define NTOK    (BATCH * SEQL)       // 4096
#define D3      (3 * DEMB)           // 6144

typedef unsigned long long ull;

// -------- scratch (__device__ globals; no allocs allowed) --------
__device__ float g_qkv [(size_t)NTOK * D3];     // 96 MB
__device__ float g_attn[(size_t)NTOK * DEMB];   // 32 MB (tf32-rounded)
__device__ float g_xtf [(size_t)NTOK * DEMB];   // 32 MB (tf32-rounded x)
__device__ float g_wT1 [(size_t)D3   * DEMB];   // 48 MB (w_in^T, tf32)
__device__ float g_wT2 [(size_t)DEMB * DEMB];   // 16 MB (w_out^T, tf32)

// ---------------- helpers ----------------
__device__ __forceinline__ uint32_t smem_u32(const void* p) {
    uint32_t a;
    asm("{ .reg .u64 t; cvta.to.shared.u64 t, %1; cvt.u32.u64 %0, t; }" : "=r"(a) : "l"(p));
    return a;
}
__device__ __forceinline__ float tf32r(float f) {
    uint32_t u = __float_as_uint(f);
    asm("cvt.rna.tf32.f32 %0, %0;" : "+r"(u));
    return __uint_as_float(u);
}
__device__ __forceinline__ ull pack2(float x, float y) {
    ull r; asm("mov.b64 %0, {%1, %2};" : "=l"(r) : "f"(x), "f"(y)); return r;
}
__device__ __forceinline__ void unpack2(ull v, float &x, float &y) {
    asm("mov.b64 {%0, %1}, %2;" : "=f"(x), "=f"(y) : "l"(v));
}
__device__ __forceinline__ void fma2(ull &d, ull a, ull b) {
    asm("fma.rn.f32x2 %0, %1, %2, %0;" : "+l"(d) : "l"(a), "l"(b));
}
__device__ __forceinline__ void mul2(ull &d, ull a) {
    asm("mul.rn.f32x2 %0, %0, %1;" : "+l"(d) : "l"(a));
}
union F4U { float4 f4; ull u[2]; float f[4]; };

__device__ __forceinline__ void cp_async16(uint32_t dst, const void* src) {
    asm volatile("cp.async.cg.shared.global [%0], [%1], 16;" :: "r"(dst), "l"(src) : "memory");
}
#define CP_COMMIT() asm volatile("cp.async.commit_group;" ::: "memory")
#define CP_WAIT(n)  asm volatile("cp.async.wait_group %0;" :: "n"(n) : "memory")

__device__ __forceinline__ void mma_tf32(float* c, const uint32_t* a, const uint32_t* b) {
    asm volatile(
        "mma.sync.aligned.m16n8k8.row.col.f32.tf32.tf32.f32 "
        "{%0,%1,%2,%3}, {%4,%5,%6,%7}, {%8,%9}, {%0,%1,%2,%3};"
        : "+f"(c[0]), "+f"(c[1]), "+f"(c[2]), "+f"(c[3])
        : "r"(a[0]), "r"(a[1]), "r"(a[2]), "r"(a[3]), "r"(b[0]), "r"(b[1]));
}

// ================================================================
// Prep kernels: tf32-round inputs, transpose weights to [N][K]
// ================================================================
__global__ void transpose_tf32_kernel(const float* __restrict__ src, float* __restrict__ dst,
                                      int R, int C) {
    // src [R][C] -> dst [C][R], values rounded to tf32
    __shared__ float tile[32][33];
    int bx = blockIdx.x * 32, by = blockIdx.y * 32;
    int x = bx + threadIdx.x;
    for (int i = threadIdx.y; i < 32; i += 8)
        tile[i][threadIdx.x] = src[(size_t)(by + i) * C + x];
    __syncthreads();
    int ox = by + threadIdx.x;
    for (int i = threadIdx.y; i < 32; i += 8)
        dst[(size_t)(bx + i) * R + ox] = tf32r(tile[threadIdx.x][i]);
}

__global__ void conv_tf32_kernel(const float* __restrict__ src, float* __restrict__ dst, int n4) {
    int i = blockIdx.x * blockDim.x + threadIdx.x;
    if (i < n4) {
        float4 v = ((const float4*)src)[i];
        v.x = tf32r(v.x); v.y = tf32r(v.y); v.z = tf32r(v.z); v.w = tf32r(v.w);
        ((float4*)dst)[i] = v;
    }
}

// ================================================================
// tf32 mma.sync GEMM: C[M,N] = A[M,K] @ Bt[N,K]^T + bias[N]
// CTA 128x128, 8 warps (warp tile 64x32), K-chunk 32, 2-stage cp.async.
// A, Bt pre-rounded to tf32. M%128==0, N%128==0, K%32==0.
// ================================================================
#define LDT 36                         // padded row (floats)
#define STG_F (2 * 128 * LDT)          // floats per stage (A + B)
#define GEMM_SMEM (2 * STG_F * (int)sizeof(float))   // 73728 B

__global__ __launch_bounds__(256, 2) void tf32_mma_gemm_kernel(
    const float* __restrict__ A, const float* __restrict__ Bt,
    const float* __restrict__ bias, float* __restrict__ C,
    int M, int N, int K)
{
    extern __shared__ float sm[];
    const int tid  = threadIdx.x;
    const int lane = tid & 31;
    const int wid  = tid >> 5;
    const int wm = wid >> 2;           // 0..1  -> 64-row slab
    const int wn = wid & 3;            // 0..3  -> 32-col slab
    const int g = lane >> 2, t = lane & 3;
    const int bm = blockIdx.x * 128;
    const int bn = blockIdx.y * 128;
    const int nchunks = K >> 5;

    float acc[4][4][4];
    #pragma unroll
    for (int mi = 0; mi < 4; mi++)
        #pragma unroll
        for (int ni = 0; ni < 4; ni++)
            #pragma unroll
            for (int q = 0; q < 4; q++) acc[mi][ni][q] = 0.0f;

    // ---- stage loader (cp.async) ----
    auto load_stage = [&](int c, int p) {
        const int kb = c << 5;
        float* dstA = sm + p * STG_F;
        float* dstB = dstA + 128 * LDT;
        #pragma unroll
        for (int i = 0; i < 4; i++) {
            int idx = tid + i * 256;           // 0..1023
            int row = idx >> 3;                // 0..127
            int c4  = (idx & 7) << 2;          // 0..28
            cp_async16(smem_u32(dstA + row * LDT + c4),
                       A + (size_t)(bm + row) * K + kb + c4);
            cp_async16(smem_u32(dstB + row * LDT + c4),
                       Bt + (size_t)(bn + row) * K + kb + c4);
        }
        CP_COMMIT();
    };

    load_stage(0, 0);

    for (int c = 0; c < nchunks; c++) {
        const int p = c & 1;
        if (c + 1 < nchunks) {
            load_stage(c + 1, p ^ 1);
            CP_WAIT(1);
        } else {
            CP_WAIT(0);
        }
        __syncthreads();

        const float* sA = sm + p * STG_F;
        const float* sB = sA + 128 * LDT;
        #pragma unroll
        for (int ks = 0; ks < 4; ks++) {
            const int kb = ks * 8;
            uint32_t af[4][4], bf[4][2];
            #pragma unroll
            for (int mi = 0; mi < 4; mi++) {
                const float* base = sA + (wm * 64 + mi * 16 + g) * LDT + kb + t;
                af[mi][0] = __float_as_uint(base[0]);
                af[mi][1] = __float_as_uint(base[8 * LDT]);
                af[mi][2] = __float_as_uint(base[4]);
                af[mi][3] = __float_as_uint(base[8 * LDT + 4]);
            }
            #pragma unroll
            for (int ni = 0; ni < 4; ni++) {
                const float* base = sB + (wn * 32 + ni * 8 + g) * LDT + kb + t;
                bf[ni][0] = __float_as_uint(base[0]);
                bf[ni][1] = __float_as_uint(base[4]);
            }
            #pragma unroll
            for (int mi = 0; mi < 4; mi++)
                #pragma unroll
                for (int ni = 0; ni < 4; ni++)
                    mma_tf32(acc[mi][ni], af[mi], bf[ni]);
        }
        __syncthreads();
    }

    // ---- epilogue: add bias, store ----
    #pragma unroll
    for (int mi = 0; mi < 4; mi++) {
        const int r0 = bm + wm * 64 + mi * 16 + g;
        #pragma unroll
        for (int ni = 0; ni < 4; ni++) {
            const int n = bn + wn * 32 + ni * 8 + t * 2;
            float2 bv = *(const float2*)(bias + n);
            float2 v0 = make_float2(acc[mi][ni][0] + bv.x, acc[mi][ni][1] + bv.y);
            float2 v1 = make_float2(acc[mi][ni][2] + bv.x, acc[mi][ni][3] + bv.y);
            *(float2*)(C + (size_t)r0 * N + n)       = v0;
            *(float2*)(C + (size_t)(r0 + 8) * N + n) = v1;
        }
    }
}

// ================================================================
// Causal flash attention, fp32 SIMT (unchanged from R1; tf32 output)
// ================================================================
#define LDS_S 132
#define FLASH_SMEM ((3 * 128 * LDS_S + 3 * 128) * (int)sizeof(float))

__global__ __launch_bounds__(256, 1) void flash_attn_kernel(
    const float* __restrict__ qkv, float* __restrict__ attn_out)
{
    extern __shared__ float smf[];
    float* Qs  = smf;
    float* KPs = Qs  + 128 * LDS_S;
    float* Vs  = KPs + 128 * LDS_S;
    float* m_s = Vs  + 128 * LDS_S;
    float* l_s = m_s + 128;
    float* f_s = l_s + 128;

    const int qt  = (int)gridDim.x - 1 - (int)blockIdx.x;
    const int h   = blockIdx.y;
    const int b   = blockIdx.z;
    const int tid = threadIdx.x;
    const int tx = tid & 15, ty = tid >> 4;
    const int r0 = ty * 8, c0 = tx * 8;
    const float scale = 0.08838834764831845f;

    #pragma unroll
    for (int it = 0; it < 16; it++) {
        int idx = tid + it * 256;
        int r  = idx >> 5;
        int c4 = (idx & 31) * 4;
        float4 f = *(const float4*)(qkv + (size_t)(b * SEQL + qt * 128 + r) * D3 + h * DHEAD + c4);
        Qs[(c4 + 0) * LDS_S + r] = f.x; Qs[(c4 + 1) * LDS_S + r] = f.y;
        Qs[(c4 + 2) * LDS_S + r] = f.z; Qs[(c4 + 3) * LDS_S + r] = f.w;
    }
    if (tid < 128) { m_s[tid] = -INFINITY; l_s[tid] = 0.0f; }

    ull o2[8][4];
    #pragma unroll
    for (int i = 0; i < 8; i++)
        #pragma unroll
        for (int j = 0; j < 4; j++) o2[i][j] = 0ull;

    __syncthreads();

    for (int jt = 0; jt <= qt; jt++) {
        #pragma unroll
        for (int it = 0; it < 16; it++) {
            int idx = tid + it * 256;
            int r  = idx >> 5;
            int c4 = (idx & 31) * 4;
            size_t go = (size_t)(b * SEQL + jt * 128 + r) * D3 + h * DHEAD + c4;
            float4 kf = *(const float4*)(qkv + go + DEMB);
            KPs[(c4 + 0) * LDS_S + r] = kf.x; KPs[(c4 + 1) * LDS_S + r] = kf.y;
            KPs[(c4 + 2) * LDS_S + r] = kf.z; KPs[(c4 + 3) * LDS_S + r] = kf.w;
            *(float4*)&Vs[r * LDS_S + c4] = *(const float4*)(qkv + go + 2 * DEMB);
        }
        __syncthreads();

        ull s2[8][4];
        #pragma unroll
        for (int i = 0; i < 8; i++)
            #pragma unroll
            for (int j = 0; j < 4; j++) s2[i][j] = 0ull;

        for (int k = 0; k < 128; k++) {
            F4U a0, a1, b0, b1;
            a0.f4 = *(const float4*)&Qs[k * LDS_S + r0];
            a1.f4 = *(const float4*)&Qs[k * LDS_S + r0 + 4];
            b0.f4 = *(const float4*)&KPs[k * LDS_S + c0];
            b1.f4 = *(const float4*)&KPs[k * LDS_S + c0 + 4];
            ull bb[4] = { b0.u[0], b0.u[1], b1.u[0], b1.u[1] };
            #pragma unroll
            for (int i = 0; i < 8; i++) {
                float av = (i < 4) ? a0.f[i] : a1.f[i - 4];
                ull ad = pack2(av, av);
                #pragma unroll
                for (int j = 0; j < 4; j++) fma2(s2[i][j], ad, bb[j]);
            }
        }

        float sc[8][8];
        #pragma unroll
        for (int i = 0; i < 8; i++)
            #pragma unroll
            for (int j = 0; j < 4; j++) unpack2(s2[i][j], sc[i][2 * j], sc[i][2 * j + 1]);
        if (jt == qt) {
            #pragma unroll
            for (int i = 0; i < 8; i++)
                #pragma unroll
                for (int j = 0; j < 8; j++)
                    if (c0 + j > r0 + i) sc[i][j] = -INFINITY;
        }
        #pragma unroll
        for (int i = 0; i < 8; i++)
            #pragma unroll
            for (int j = 0; j < 8; j++) sc[i][j] *= scale;

        __syncthreads();

        #pragma unroll
        for (int j = 0; j < 8; j++) {
            float4 p0 = make_float4(sc[0][j], sc[1][j], sc[2][j], sc[3][j]);
            float4 p1 = make_float4(sc[4][j], sc[5][j], sc[6][j], sc[7][j]);
            *(float4*)&KPs[(c0 + j) * LDS_S + r0]     = p0;
            *(float4*)&KPs[(c0 + j) * LDS_S + r0 + 4] = p1;
        }
        __syncthreads();

        if (tid < 128) {
            const int q = tid;
            float mo = m_s[q], lo = l_s[q];
            float mt = -INFINITY;
            #pragma unroll 4
            for (int c = 0; c < 128; c++) mt = fmaxf(mt, KPs[c * LDS_S + q]);
            float mn = fmaxf(mo, mt);
            float f = __expf(mo - mn);
            float ssum = 0.0f;
            #pragma unroll 4
            for (int c = 0; c < 128; c++) {
                float p = __expf(KPs[c * LDS_S + q] - mn);
                KPs[c * LDS_S + q] = p;
                ssum += p;
            }
            m_s[q] = mn;
            l_s[q] = lo * f + ssum;
            f_s[q] = f;
        }
        __syncthreads();

        #pragma unroll
        for (int i = 0; i < 8; i++) {
            float fv = f_s[r0 + i];
            ull fd = pack2(fv, fv);
            #pragma unroll
            for (int j = 0; j < 4; j++) mul2(o2[i][j], fd);
        }
        for (int kk = 0; kk < 128; kk++) {
            F4U a0, a1, b0, b1;
            a0.f4 = *(const float4*)&KPs[kk * LDS_S + r0];
            a1.f4 = *(const float4*)&KPs[kk * LDS_S + r0 + 4];
            b0.f4 = *(const float4*)&Vs[kk * LDS_S + c0];
            b1.f4 = *(const float4*)&Vs[kk * LDS_S + c0 + 4];
            ull bb[4] = { b0.u[0], b0.u[1], b1.u[0], b1.u[1] };
            #pragma unroll
            for (int i = 0; i < 8; i++) {
                float av = (i < 4) ? a0.f[i] : a1.f[i - 4];
                ull ad = pack2(av, av);
                #pragma unroll
                for (int j = 0; j < 4; j++) fma2(o2[i][j], ad, bb[j]);
            }
        }
        __syncthreads();
    }

    // finalize: O /= l, round to tf32 (feeds tf32 out-proj GEMM), store
    #pragma unroll
    for (int i = 0; i < 8; i++) {
        float inv = 1.0f / l_s[r0 + i];
        float r[8];
        #pragma unroll
        for (int j = 0; j < 4; j++) unpack2(o2[i][j], r[2 * j], r[2 * j + 1]);
        float4 o0 = make_float4(tf32r(r[0] * inv), tf32r(r[1] * inv),
                                tf32r(r[2] * inv), tf32r(r[3] * inv));
        float4 o1 = make_float4(tf32r(r[4] * inv), tf32r(r[5] * inv),
                                tf32r(r[6] * inv), tf32r(r[7] * inv));
        size_t off = (size_t)(b * SEQL + qt * 128 + r0 + i) * DEMB + h * DHEAD + c0;
        *(float4*)(attn_out + off)     = o0;
        *(float4*)(attn_out + off + 4) = o1;
    }
}

// ================================================================
// Launcher
// ================================================================
extern "C" void kernel_launch(void* const* d_in, const int* in_sizes, int n_in,
                              void* d_out, int out_size)
{
    (void)in_sizes; (void)n_in; (void)out_size;
    const float* x     = (const float*)d_in[0];
    const float* w_in  = (const float*)d_in[1];
    const float* b_in  = (const float*)d_in[2];
    const float* w_out = (const float*)d_in[3];
    const float* b_out = (const float*)d_in[4];
    float* out = (float*)d_out;

    void *qkv_p, *attn_p, *xtf_p, *wT1_p, *wT2_p;
    cudaGetSymbolAddress(&qkv_p,  g_qkv);
    cudaGetSymbolAddress(&attn_p, g_attn);
    cudaGetSymbolAddress(&xtf_p,  g_xtf);
    cudaGetSymbolAddress(&wT1_p,  g_wT1);
    cudaGetSymbolAddress(&wT2_p,  g_wT2);

    cudaFuncSetAttribute(flash_attn_kernel,
                         cudaFuncAttributeMaxDynamicSharedMemorySize, FLASH_SMEM);
    cudaFuncSetAttribute(tf32_mma_gemm_kernel,
                         cudaFuncAttributeMaxDynamicSharedMemorySize, GEMM_SMEM);

    // prep: wT1 = tf32(w_in^T), wT2 = tf32(w_out^T), xtf = tf32(x)
    transpose_tf32_kernel<<<dim3(D3 / 32, DEMB / 32), dim3(32, 8)>>>(w_in, (float*)wT1_p, DEMB, D3);
    transpose_tf32_kernel<<<dim3(DEMB / 32, DEMB / 32), dim3(32, 8)>>>(w_out, (float*)wT2_p, DEMB, DEMB);
    conv_tf32_kernel<<<(NTOK * DEMB / 4 + 255) / 256, 256>>>(x, (float*)xtf_p, NTOK * DEMB / 4);

    // 1) qkv = x @ w_in + b_in   [4096, 6144]  (tf32 tensor cores)
    tf32_mma_gemm_kernel<<<dim3(NTOK / 128, D3 / 128), 256, GEMM_SMEM>>>(
        (const float*)xtf_p, (const float*)wT1_p, b_in, (float*)qkv_p, NTOK, D3, DEMB);

    // 2) causal flash attention -> g_attn (tf32-rounded)
    flash_attn_kernel<<<dim3(SEQL / 128, NHEADS, BATCH), 256, FLASH_SMEM>>>(
        (const float*)qkv_p, (float*)attn_p);

    // 3) out = attn @ w_out + b_out  [4096, 2048]
    tf32_mma_gemm_kernel<<<dim3(NTOK / 128, DEMB / 128), 256, GEMM_SMEM>>>(
        (const float*)attn_p, (const float*)wT2_p, b_out, out, NTOK, DEMB, DEMB);
}

// round 4
// speedup vs baseline: 3.3824x; 1.7529x over previous
#include <cuda_runtime.h>
#include <math.h>
#include <stdint.h>

#define BATCH   2
#define SEQL    2048
#define DEMB    2048
#define NHEADS  16
#define DHEAD   128
#define NTOK    (BATCH * SEQL)       // 4096
#define D3      (3 * DEMB)           // 6144

// combined score scale: log2(e)/sqrt(128), folded into Q at GEMM1 epilogue
#define QSC 0.1275174446f
#define NEGINF __int_as_float(0xff800000)

typedef unsigned long long ull;

// -------- scratch (__device__ globals; no allocs allowed) --------
__device__ float g_qkv [(size_t)NTOK * D3];     // 96 MB (tf32, Q pre-scaled)
__device__ float g_attn[(size_t)NTOK * DEMB];   // 32 MB (tf32-rounded)
__device__ float g_xtf [(size_t)NTOK * DEMB];   // 32 MB (tf32-rounded x)
__device__ float g_wT1 [(size_t)D3   * DEMB];   // 48 MB (w_in^T, tf32)
__device__ float g_wT2 [(size_t)DEMB * DEMB];   // 16 MB (w_out^T, tf32)

// ---------------- helpers ----------------
__device__ __forceinline__ uint32_t smem_u32(const void* p) {
    uint32_t a;
    asm("{ .reg .u64 t; cvta.to.shared.u64 t, %1; cvt.u32.u64 %0, t; }" : "=r"(a) : "l"(p));
    return a;
}
__device__ __forceinline__ float tf32r(float f) {
    uint32_t u = __float_as_uint(f);
    asm("cvt.rna.tf32.f32 %0, %0;" : "+r"(u));
    return __uint_as_float(u);
}
__device__ __forceinline__ float ex2(float x) {
    float y; asm("ex2.approx.f32 %0, %1;" : "=f"(y) : "f"(x)); return y;
}
__device__ __forceinline__ void cp_async16(uint32_t dst, const void* src) {
    asm volatile("cp.async.cg.shared.global [%0], [%1], 16;" :: "r"(dst), "l"(src) : "memory");
}
#define CP_COMMIT() asm volatile("cp.async.commit_group;" ::: "memory")
#define CP_WAIT(n)  asm volatile("cp.async.wait_group %0;" :: "n"(n) : "memory")

__device__ __forceinline__ void mma_tf32(float* c, const uint32_t* a, const uint32_t* b) {
    asm volatile(
        "mma.sync.aligned.m16n8k8.row.col.f32.tf32.tf32.f32 "
        "{%0,%1,%2,%3}, {%4,%5,%6,%7}, {%8,%9}, {%0,%1,%2,%3};"
        : "+f"(c[0]), "+f"(c[1]), "+f"(c[2]), "+f"(c[3])
        : "r"(a[0]), "r"(a[1]), "r"(a[2]), "r"(a[3]), "r"(b[0]), "r"(b[1]));
}

// ================================================================
// Prep kernels: tf32-round inputs, transpose weights to [N][K]
// ================================================================
__global__ void transpose_tf32_kernel(const float* __restrict__ src, float* __restrict__ dst,
                                      int R, int C) {
    __shared__ float tile[32][33];
    int bx = blockIdx.x * 32, by = blockIdx.y * 32;
    int x = bx + threadIdx.x;
    for (int i = threadIdx.y; i < 32; i += 8)
        tile[i][threadIdx.x] = src[(size_t)(by + i) * C + x];
    __syncthreads();
    int ox = by + threadIdx.x;
    for (int i = threadIdx.y; i < 32; i += 8)
        dst[(size_t)(bx + i) * R + ox] = tf32r(tile[threadIdx.x][i]);
}

__global__ void conv_tf32_kernel(const float* __restrict__ src, float* __restrict__ dst, int n4) {
    int i = blockIdx.x * blockDim.x + threadIdx.x;
    if (i < n4) {
        float4 v = ((const float4*)src)[i];
        v.x = tf32r(v.x); v.y = tf32r(v.y); v.z = tf32r(v.z); v.w = tf32r(v.w);
        ((float4*)dst)[i] = v;
    }
}

// ================================================================
// tf32 mma.sync GEMM: C[M,N] = A[M,K] @ Bt[N,K]^T + bias[N]
// Epilogue options: cols < qcols get *= QSC; round_out -> tf32r.
// ================================================================
#define LDT 36
#define STG_F (2 * 128 * LDT)
#define GEMM_SMEM (2 * STG_F * (int)sizeof(float))

__global__ __launch_bounds__(256, 2) void tf32_mma_gemm_kernel(
    const float* __restrict__ A, const float* __restrict__ Bt,
    const float* __restrict__ bias, float* __restrict__ C,
    int M, int N, int K, int qcols, int round_out)
{
    extern __shared__ float sm[];
    const int tid  = threadIdx.x;
    const int lane = tid & 31;
    const int wid  = tid >> 5;
    const int wm = wid >> 2;
    const int wn = wid & 3;
    const int g = lane >> 2, t = lane & 3;
    const int bm = blockIdx.x * 128;
    const int bn = blockIdx.y * 128;
    const int nchunks = K >> 5;

    float acc[4][4][4];
    #pragma unroll
    for (int mi = 0; mi < 4; mi++)
        #pragma unroll
        for (int ni = 0; ni < 4; ni++)
            #pragma unroll
            for (int q = 0; q < 4; q++) acc[mi][ni][q] = 0.0f;

    auto load_stage = [&](int c, int p) {
        const int kb = c << 5;
        float* dstA = sm + p * STG_F;
        float* dstB = dstA + 128 * LDT;
        #pragma unroll
        for (int i = 0; i < 4; i++) {
            int idx = tid + i * 256;
            int row = idx >> 3;
            int c4  = (idx & 7) << 2;
            cp_async16(smem_u32(dstA + row * LDT + c4),
                       A + (size_t)(bm + row) * K + kb + c4);
            cp_async16(smem_u32(dstB + row * LDT + c4),
                       Bt + (size_t)(bn + row) * K + kb + c4);
        }
        CP_COMMIT();
    };

    load_stage(0, 0);

    for (int c = 0; c < nchunks; c++) {
        const int p = c & 1;
        if (c + 1 < nchunks) {
            load_stage(c + 1, p ^ 1);
            CP_WAIT(1);
        } else {
            CP_WAIT(0);
        }
        __syncthreads();

        const float* sA = sm + p * STG_F;
        const float* sB = sA + 128 * LDT;
        #pragma unroll
        for (int ks = 0; ks < 4; ks++) {
            const int kb = ks * 8;
            uint32_t af[4][4], bf[4][2];
            #pragma unroll
            for (int mi = 0; mi < 4; mi++) {
                const float* base = sA + (wm * 64 + mi * 16 + g) * LDT + kb + t;
                af[mi][0] = __float_as_uint(base[0]);
                af[mi][1] = __float_as_uint(base[8 * LDT]);
                af[mi][2] = __float_as_uint(base[4]);
                af[mi][3] = __float_as_uint(base[8 * LDT + 4]);
            }
            #pragma unroll
            for (int ni = 0; ni < 4; ni++) {
                const float* base = sB + (wn * 32 + ni * 8 + g) * LDT + kb + t;
                bf[ni][0] = __float_as_uint(base[0]);
                bf[ni][1] = __float_as_uint(base[4]);
            }
            #pragma unroll
            for (int mi = 0; mi < 4; mi++)
                #pragma unroll
                for (int ni = 0; ni < 4; ni++)
                    mma_tf32(acc[mi][ni], af[mi], bf[ni]);
        }
        __syncthreads();
    }

    #pragma unroll
    for (int mi = 0; mi < 4; mi++) {
        const int r0 = bm + wm * 64 + mi * 16 + g;
        #pragma unroll
        for (int ni = 0; ni < 4; ni++) {
            const int n = bn + wn * 32 + ni * 8 + t * 2;
            const float sc = (n < qcols) ? QSC : 1.0f;
            float2 bv = *(const float2*)(bias + n);
            float v0 = (acc[mi][ni][0] + bv.x) * sc;
            float v1 = (acc[mi][ni][1] + bv.y) * sc;
            float v2 = (acc[mi][ni][2] + bv.x) * sc;
            float v3 = (acc[mi][ni][3] + bv.y) * sc;
            if (round_out) { v0 = tf32r(v0); v1 = tf32r(v1); v2 = tf32r(v2); v3 = tf32r(v3); }
            *(float2*)(C + (size_t)r0 * N + n)       = make_float2(v0, v1);
            *(float2*)(C + (size_t)(r0 + 8) * N + n) = make_float2(v2, v3);
        }
    }
}

// ================================================================
// Flash attention on mma.sync tf32.
// CTA: 256 thr / 8 warps; tile 128q x 128kv; dh = 128.
// Warp grid: wm(2) x wn(4); S warp tile 64x32, O warp tile 64x32(dh).
// smem: Qs[128][132], KPs[128][132] (K then P), Vs[128][132],
//       red_m[4][128], red_s[4][128].
// ================================================================
#define LDP 132
#define FL_K  (128 * LDP)
#define FL_V  (2 * 128 * LDP)
#define FL_RM (3 * 128 * LDP)
#define FL_RS (FL_RM + 512)
#define FLASH_SMEM ((FL_RS + 512) * (int)sizeof(float))   // 206848 B

__global__ __launch_bounds__(256, 1) void flash_mma_kernel(
    const float* __restrict__ qkv, float* __restrict__ attn_out)
{
    extern __shared__ float sm[];
    float* Qs    = sm;
    float* KPs   = sm + FL_K;
    float* Vs    = sm + FL_V;
    float* red_m = sm + FL_RM;
    float* red_s = sm + FL_RS;

    const int qt  = (int)gridDim.x - 1 - (int)blockIdx.x;   // heavy first
    const int h   = blockIdx.y;
    const int b   = blockIdx.z;
    const int tid  = threadIdx.x;
    const int lane = tid & 31;
    const int wid  = tid >> 5;
    const int wm = wid >> 2, wn = wid & 3;
    const int g = lane >> 2, t = lane & 3;

    // ---- Q tile load (once), group 0 ----
    const float* qbase = qkv + (size_t)(b * SEQL + qt * 128) * D3 + h * DHEAD;
    #pragma unroll
    for (int i = 0; i < 16; i++) {
        int idx = tid + i * 256;
        int r  = idx >> 5;
        int c4 = (idx & 31) * 4;
        cp_async16(smem_u32(Qs + r * LDP + c4), qbase + (size_t)r * D3 + c4);
    }
    CP_COMMIT();

    float o[4][4][4];
    #pragma unroll
    for (int mi = 0; mi < 4; mi++)
        #pragma unroll
        for (int ni = 0; ni < 4; ni++)
            #pragma unroll
            for (int q = 0; q < 4; q++) o[mi][ni][q] = 0.0f;
    float mrow[4][2], lrow[4][2];
    #pragma unroll
    for (int mi = 0; mi < 4; mi++) {
        mrow[mi][0] = NEGINF; mrow[mi][1] = NEGINF;
        lrow[mi][0] = 0.0f;   lrow[mi][1] = 0.0f;
    }

    for (int jt = 0; jt <= qt; jt++) {
        // ---- K tile (group), then V tile (group) ----
        const float* kbase = qkv + (size_t)(b * SEQL + jt * 128) * D3 + DEMB + h * DHEAD;
        #pragma unroll
        for (int i = 0; i < 16; i++) {
            int idx = tid + i * 256;
            int r  = idx >> 5;
            int c4 = (idx & 31) * 4;
            cp_async16(smem_u32(KPs + r * LDP + c4), kbase + (size_t)r * D3 + c4);
        }
        CP_COMMIT();
        #pragma unroll
        for (int i = 0; i < 16; i++) {
            int idx = tid + i * 256;
            int r  = idx >> 5;
            int c4 = (idx & 31) * 4;
            cp_async16(smem_u32(Vs + r * LDP + c4), kbase + DEMB + (size_t)r * D3 + c4);
        }
        CP_COMMIT();
        CP_WAIT(1);           // Q + K arrived (V may be in flight)
        __syncthreads();

        // ---- S = Q @ K^T ----
        float s[4][4][4];
        #pragma unroll
        for (int mi = 0; mi < 4; mi++)
            #pragma unroll
            for (int ni = 0; ni < 4; ni++)
                #pragma unroll
                for (int q = 0; q < 4; q++) s[mi][ni][q] = 0.0f;

        #pragma unroll
        for (int ks = 0; ks < 16; ks++) {
            const int kb = ks * 8;
            uint32_t af[4][4], bf[4][2];
            #pragma unroll
            for (int mi = 0; mi < 4; mi++) {
                const float* base = Qs + (wm * 64 + mi * 16 + g) * LDP + kb + t;
                af[mi][0] = __float_as_uint(base[0]);
                af[mi][1] = __float_as_uint(base[8 * LDP]);
                af[mi][2] = __float_as_uint(base[4]);
                af[mi][3] = __float_as_uint(base[8 * LDP + 4]);
            }
            #pragma unroll
            for (int ni = 0; ni < 4; ni++) {
                const float* base = KPs + (wn * 32 + ni * 8 + g) * LDP + kb + t;
                bf[ni][0] = __float_as_uint(base[0]);
                bf[ni][1] = __float_as_uint(base[4]);
            }
            #pragma unroll
            for (int mi = 0; mi < 4; mi++)
                #pragma unroll
                for (int ni = 0; ni < 4; ni++)
                    mma_tf32(s[mi][ni], af[mi], bf[ni]);
        }

        // ---- causal mask on diagonal tile ----
        if (jt == qt) {
            #pragma unroll
            for (int mi = 0; mi < 4; mi++) {
                const int r0 = wm * 64 + mi * 16 + g;
                #pragma unroll
                for (int ni = 0; ni < 4; ni++) {
                    const int c = wn * 32 + ni * 8 + 2 * t;
                    if (c     > r0)     s[mi][ni][0] = NEGINF;
                    if (c + 1 > r0)     s[mi][ni][1] = NEGINF;
                    if (c     > r0 + 8) s[mi][ni][2] = NEGINF;
                    if (c + 1 > r0 + 8) s[mi][ni][3] = NEGINF;
                }
            }
        }

        // ---- row max: in-thread -> quad shfl -> cross-warp smem ----
        float mt[4][2];
        #pragma unroll
        for (int mi = 0; mi < 4; mi++) {
            float a = fmaxf(s[mi][0][0], s[mi][0][1]);
            float bq = fmaxf(s[mi][0][2], s[mi][0][3]);
            #pragma unroll
            for (int ni = 1; ni < 4; ni++) {
                a  = fmaxf(a,  fmaxf(s[mi][ni][0], s[mi][ni][1]));
                bq = fmaxf(bq, fmaxf(s[mi][ni][2], s[mi][ni][3]));
            }
            mt[mi][0] = a; mt[mi][1] = bq;
        }
        #pragma unroll
        for (int off = 1; off <= 2; off <<= 1) {
            #pragma unroll
            for (int mi = 0; mi < 4; mi++) {
                mt[mi][0] = fmaxf(mt[mi][0], __shfl_xor_sync(0xffffffffu, mt[mi][0], off));
                mt[mi][1] = fmaxf(mt[mi][1], __shfl_xor_sync(0xffffffffu, mt[mi][1], off));
            }
        }
        if (t == 0) {
            #pragma unroll
            for (int mi = 0; mi < 4; mi++) {
                red_m[wn * 128 + wm * 64 + mi * 16 + g]     = mt[mi][0];
                red_m[wn * 128 + wm * 64 + mi * 16 + g + 8] = mt[mi][1];
            }
        }
        __syncthreads();

        float mnew[4][2], fsc[4][2];
        #pragma unroll
        for (int mi = 0; mi < 4; mi++) {
            #pragma unroll
            for (int hh = 0; hh < 2; hh++) {
                const int row = wm * 64 + mi * 16 + g + 8 * hh;
                float v = fmaxf(fmaxf(red_m[row], red_m[128 + row]),
                                fmaxf(red_m[256 + row], red_m[384 + row]));
                float mn = fmaxf(mrow[mi][hh], v);
                fsc[mi][hh]  = ex2(mrow[mi][hh] - mn);   // 0 on first tile
                mnew[mi][hh] = mn;
                mrow[mi][hh] = mn;
            }
        }

        // ---- exp (base 2; scale folded into Q) + row sums ----
        float rs[4][2];
        #pragma unroll
        for (int mi = 0; mi < 4; mi++) { rs[mi][0] = 0.0f; rs[mi][1] = 0.0f; }
        #pragma unroll
        for (int mi = 0; mi < 4; mi++) {
            #pragma unroll
            for (int ni = 0; ni < 4; ni++) {
                s[mi][ni][0] = ex2(s[mi][ni][0] - mnew[mi][0]);
                s[mi][ni][1] = ex2(s[mi][ni][1] - mnew[mi][0]);
                s[mi][ni][2] = ex2(s[mi][ni][2] - mnew[mi][1]);
                s[mi][ni][3] = ex2(s[mi][ni][3] - mnew[mi][1]);
                rs[mi][0] += s[mi][ni][0] + s[mi][ni][1];
                rs[mi][1] += s[mi][ni][2] + s[mi][ni][3];
            }
        }
        #pragma unroll
        for (int off = 1; off <= 2; off <<= 1) {
            #pragma unroll
            for (int mi = 0; mi < 4; mi++) {
                rs[mi][0] += __shfl_xor_sync(0xffffffffu, rs[mi][0], off);
                rs[mi][1] += __shfl_xor_sync(0xffffffffu, rs[mi][1], off);
            }
        }
        if (t == 0) {
            #pragma unroll
            for (int mi = 0; mi < 4; mi++) {
                red_s[wn * 128 + wm * 64 + mi * 16 + g]     = rs[mi][0];
                red_s[wn * 128 + wm * 64 + mi * 16 + g + 8] = rs[mi][1];
            }
        }

        // ---- P (tf32) -> smem (reuse K buffer; safe: last K read was
        //      before the red_m __syncthreads above) ----
        #pragma unroll
        for (int mi = 0; mi < 4; mi++) {
            const int r0 = wm * 64 + mi * 16 + g;
            #pragma unroll
            for (int ni = 0; ni < 4; ni++) {
                const int c = wn * 32 + ni * 8 + 2 * t;
                *(float2*)&KPs[r0 * LDP + c] =
                    make_float2(tf32r(s[mi][ni][0]), tf32r(s[mi][ni][1]));
                *(float2*)&KPs[(r0 + 8) * LDP + c] =
                    make_float2(tf32r(s[mi][ni][2]), tf32r(s[mi][ni][3]));
            }
        }
        CP_WAIT(0);            // V arrived (this thread's part)
        __syncthreads();       // P + V + red_s visible to all

        // ---- read row sums, update l, rescale O ----
        #pragma unroll
        for (int mi = 0; mi < 4; mi++) {
            #pragma unroll
            for (int hh = 0; hh < 2; hh++) {
                const int row = wm * 64 + mi * 16 + g + 8 * hh;
                float sum = red_s[row] + red_s[128 + row] + red_s[256 + row] + red_s[384 + row];
                lrow[mi][hh] = lrow[mi][hh] * fsc[mi][hh] + sum;
            }
            #pragma unroll
            for (int ni = 0; ni < 4; ni++) {
                o[mi][ni][0] *= fsc[mi][0];
                o[mi][ni][1] *= fsc[mi][0];
                o[mi][ni][2] *= fsc[mi][1];
                o[mi][ni][3] *= fsc[mi][1];
            }
        }

        // ---- O += P @ V ----
        #pragma unroll
        for (int ks = 0; ks < 16; ks++) {
            const int kb = ks * 8;
            uint32_t af[4][4], bf[4][2];
            #pragma unroll
            for (int mi = 0; mi < 4; mi++) {
                const float* base = KPs + (wm * 64 + mi * 16 + g) * LDP + kb + t;
                af[mi][0] = __float_as_uint(base[0]);
                af[mi][1] = __float_as_uint(base[8 * LDP]);
                af[mi][2] = __float_as_uint(base[4]);
                af[mi][3] = __float_as_uint(base[8 * LDP + 4]);
            }
            #pragma unroll
            for (int ni = 0; ni < 4; ni++) {
                const int n = wn * 32 + ni * 8 + g;
                bf[ni][0] = __float_as_uint(Vs[(kb + t) * LDP + n]);
                bf[ni][1] = __float_as_uint(Vs[(kb + t + 4) * LDP + n]);
            }
            #pragma unroll
            for (int mi = 0; mi < 4; mi++)
                #pragma unroll
                for (int ni = 0; ni < 4; ni++)
                    mma_tf32(o[mi][ni], af[mi], bf[ni]);
        }
        __syncthreads();       // before next tile's cp.async overwrites KPs/Vs
    }

    // ---- epilogue: O /= l, tf32-round (feeds GEMM2), store ----
    const size_t orow = (size_t)(b * SEQL + qt * 128);
    #pragma unroll
    for (int mi = 0; mi < 4; mi++) {
        const float i0 = 1.0f / lrow[mi][0];
        const float i1 = 1.0f / lrow[mi][1];
        const int r0 = wm * 64 + mi * 16 + g;
        #pragma unroll
        for (int ni = 0; ni < 4; ni++) {
            const int cc = h * DHEAD + wn * 32 + ni * 8 + 2 * t;
            *(float2*)(attn_out + (orow + r0) * DEMB + cc) =
                make_float2(tf32r(o[mi][ni][0] * i0), tf32r(o[mi][ni][1] * i0));
            *(float2*)(attn_out + (orow + r0 + 8) * DEMB + cc) =
                make_float2(tf32r(o[mi][ni][2] * i1), tf32r(o[mi][ni][3] * i1));
        }
    }
}

// ================================================================
// Launcher
// ================================================================
extern "C" void kernel_launch(void* const* d_in, const int* in_sizes, int n_in,
                              void* d_out, int out_size)
{
    (void)in_sizes; (void)n_in; (void)out_size;
    const float* x     = (const float*)d_in[0];
    const float* w_in  = (const float*)d_in[1];
    const float* b_in  = (const float*)d_in[2];
    const float* w_out = (const float*)d_in[3];
    const float* b_out = (const float*)d_in[4];
    float* out = (float*)d_out;

    void *qkv_p, *attn_p, *xtf_p, *wT1_p, *wT2_p;
    cudaGetSymbolAddress(&qkv_p,  g_qkv);
    cudaGetSymbolAddress(&attn_p, g_attn);
    cudaGetSymbolAddress(&xtf_p,  g_xtf);
    cudaGetSymbolAddress(&wT1_p,  g_wT1);
    cudaGetSymbolAddress(&wT2_p,  g_wT2);

    cudaFuncSetAttribute(flash_mma_kernel,
                         cudaFuncAttributeMaxDynamicSharedMemorySize, FLASH_SMEM);
    cudaFuncSetAttribute(tf32_mma_gemm_kernel,
                         cudaFuncAttributeMaxDynamicSharedMemorySize, GEMM_SMEM);

    // prep: wT1 = tf32(w_in^T), wT2 = tf32(w_out^T), xtf = tf32(x)
    transpose_tf32_kernel<<<dim3(D3 / 32, DEMB / 32), dim3(32, 8)>>>(w_in, (float*)wT1_p, DEMB, D3);
    transpose_tf32_kernel<<<dim3(DEMB / 32, DEMB / 32), dim3(32, 8)>>>(w_out, (float*)wT2_p, DEMB, DEMB);
    conv_tf32_kernel<<<(NTOK * DEMB / 4 + 255) / 256, 256>>>(x, (float*)xtf_p, NTOK * DEMB / 4);

    // 1) qkv = x @ w_in + b_in  (tf32-rounded out; Q cols pre-scaled by QSC)
    tf32_mma_gemm_kernel<<<dim3(NTOK / 128, D3 / 128), 256, GEMM_SMEM>>>(
        (const float*)xtf_p, (const float*)wT1_p, b_in, (float*)qkv_p,
        NTOK, D3, DEMB, DEMB, 1);

    // 2) causal flash attention (mma.sync tf32) -> g_attn (tf32-rounded)
    flash_mma_kernel<<<dim3(SEQL / 128, NHEADS, BATCH), 256, FLASH_SMEM>>>(
        (const float*)qkv_p, (float*)attn_p);

    // 3) out = attn @ w_out + b_out  (full fp32 out)
    tf32_mma_gemm_kernel<<<dim3(NTOK / 128, DEMB / 128), 256, GEMM_SMEM>>>(
        (const float*)attn_p, (const float*)wT2_p, b_out, out,
        NTOK, DEMB, DEMB, 0, 0);
}